// round 9
// baseline (speedup 1.0000x reference)
#include <cuda_runtime.h>
#include <cuda_fp16.h>
#include <cstdint>
#include <math.h>

// Problem constants
#define BB 2
#define LL 1024
#define DM 1024
#define DI 2048
#define DS 16
#define DR 64
#define NX 96          // DR + 2*DS
#define MROWS 2048     // B*L

// ---------------- scratch (device globals; no allocation allowed) -----------
__device__ float g_xz[(size_t)MROWS * 2 * DI];     // 2048 x 4096
__device__ float g_xdbl[(size_t)MROWS * NX];       // 2048 x 96
__device__ float g_delta[(size_t)MROWS * DI];      // 2048 x 2048
__device__ float g_part[(size_t)8 * MROWS * NX];   // split-K partials, GEMM2
__device__ float g_part4[(size_t)2 * MROWS * DM];  // split-K partials, GEMM4

// Plain fp16 operands (fp32-accumulate MMA; error = fp16 rounding only)
__device__ __half g_WinT[(size_t)4096 * 1024];
__device__ __half g_WxT[(size_t)128 * 2048];       // N padded 96 -> 128
__device__ __half g_WdtT[(size_t)2048 * 64];
__device__ __half g_WoutT[(size_t)1024 * 2048];
__device__ __half g_h[(size_t)2048 * 1024];
__device__ __half g_xc[(size_t)2048 * 2048];       // conv+silu out
__device__ __half g_dt[(size_t)2048 * 64];
__device__ __half g_y[(size_t)2048 * 2048];

// ---------------- helpers ----------------------------------------------------
__device__ __forceinline__ uint32_t smem_u32(const void* p) {
    uint32_t a;
    asm("{ .reg .u64 t; cvta.to.shared.u64 t, %1; cvt.u32.u64 %0, t; }" : "=r"(a) : "l"(p));
    return a;
}
__device__ __forceinline__ void cp_async16(uint32_t dst, const void* src) {
    asm volatile("cp.async.cg.shared.global [%0], [%1], 16;" :: "r"(dst), "l"(src));
}
#define CP_COMMIT() asm volatile("cp.async.commit_group;" ::: "memory")
#define CP_WAIT2()  asm volatile("cp.async.wait_group 2;" ::: "memory")

__device__ __forceinline__ void ldsm_x4(uint32_t* r, uint32_t addr) {
    asm volatile("ldmatrix.sync.aligned.m8n8.x4.shared.b16 {%0,%1,%2,%3}, [%4];"
                 : "=r"(r[0]), "=r"(r[1]), "=r"(r[2]), "=r"(r[3]) : "r"(addr));
}
__device__ __forceinline__ void mma_16816(float* c, const uint32_t* a, uint32_t b0,
                                          uint32_t b1) {
    asm volatile(
        "mma.sync.aligned.m16n8k16.row.col.f32.f16.f16.f32 "
        "{%0,%1,%2,%3}, {%4,%5,%6,%7}, {%8,%9}, {%0,%1,%2,%3};"
        : "+f"(c[0]), "+f"(c[1]), "+f"(c[2]), "+f"(c[3])
        : "r"(a[0]), "r"(a[1]), "r"(a[2]), "r"(a[3]), "r"(b0), "r"(b1));
}

__device__ __forceinline__ float softplus_f(float v) {
    return fmaxf(v, 0.f) + log1pf(__expf(-fabsf(v)));
}

// Swizzled smem byte offset inside a 128x32 fp16 tile (8KB).
__device__ __forceinline__ uint32_t tile_off(int r, int k8) {
    const int prow = r >> 1;
    const int slot = (((r & 1) << 2) | (k8 >> 3)) ^ (prow & 7);
    return (uint32_t)((prow << 7) + (slot << 4));
}

// ---------------- mma.sync GEMM ----------------------------------------------
// C[M,N] = A[M,K] @ B^T[N,K], fp16 operands, fp32 accum.
// Block 128x128, K-chunk 32, 4-stage cp.async pipeline (distance 3), one
// __syncthreads per chunk, 2 CTAs/SM.
// Split-K: gridDim.z chunks K; block z writes C + z*M*N.
#define STAGE_B 16384
#define GSMEM (4 * STAGE_B)

template <int EPI>
__global__ __launch_bounds__(256, 2) void mma_gemm(
    const __half* __restrict__ A, const __half* __restrict__ B,
    float* __restrict__ C, int N, int K, int cpz,
    const float* __restrict__ bias) {
    extern __shared__ __align__(16) char smem[];
    const uint32_t smu = smem_u32(smem);

    const int tid = threadIdx.x;
    const int lane = tid & 31;
    const int wid = tid >> 5;
    const int m0 = blockIdx.y * 128;
    const int n0 = blockIdx.x * 128;
    const int cbeg = blockIdx.z * cpz;
    float* __restrict__ Cb = C + (size_t)blockIdx.z * (size_t)MROWS * (size_t)N;

    const int wm0 = (wid & 1) * 64;
    const int wn0 = (wid >> 1) * 32;

    const int gr0 = tid >> 2, gkc = (tid & 3) * 8;
    const uint32_t d0 = tile_off(gr0, gkc);
    const uint32_t d1 = tile_off(gr0 + 64, gkc);
    const __half* Ag = A + (size_t)(m0 + gr0) * K + gkc;
    const __half* Ag2 = A + (size_t)(m0 + gr0 + 64) * K + gkc;
    const __half* Bg = B + (size_t)(n0 + gr0) * K + gkc;
    const __half* Bg2 = B + (size_t)(n0 + gr0 + 64) * K + gkc;

    auto stage_load = [&](int s, int ck) {
        const int k0 = ck * 32;
        const uint32_t sa = smu + s * STAGE_B;
        const uint32_t sb = sa + 8192;
        cp_async16(sa + d0, Ag + k0);
        cp_async16(sa + d1, Ag2 + k0);
        cp_async16(sb + d0, Bg + k0);
        cp_async16(sb + d1, Bg2 + k0);
    };

    float acc[4][4][4];
#pragma unroll
    for (int i = 0; i < 4; ++i)
#pragma unroll
        for (int j = 0; j < 4; ++j)
#pragma unroll
            for (int q = 0; q < 4; ++q) acc[i][j][q] = 0.f;

#pragma unroll
    for (int p = 0; p < 3; ++p) {
        if (p < cpz) stage_load(p, cbeg + p);
        CP_COMMIT();
    }

    const int lr = lane & 7;
    const int lb1 = (lane >> 3) & 1;
    const int lb2 = lane >> 4;
    const int ar[4] = {wm0 + 0 + lb1 * 8 + lr, wm0 + 16 + lb1 * 8 + lr,
                       wm0 + 32 + lb1 * 8 + lr, wm0 + 48 + lb1 * 8 + lr};
    const int br[2] = {wn0 + 0 + lb2 * 8 + lr, wn0 + 16 + lb2 * 8 + lr};

    for (int j = 0; j < cpz; ++j) {
        const int s = j & 3;
        CP_WAIT2();
        __syncthreads();

        if (j + 3 < cpz) stage_load((j + 3) & 3, cbeg + j + 3);
        CP_COMMIT();

        const uint32_t sa = smu + s * STAGE_B;
        const uint32_t sb = sa + 8192;
#pragma unroll
        for (int kk = 0; kk < 2; ++kk) {
            uint32_t a[4][4], b[2][4];
            const int ka = kk * 16 + lb2 * 8;
            const int kb = kk * 16 + lb1 * 8;
#pragma unroll
            for (int mt = 0; mt < 4; ++mt) ldsm_x4(a[mt], sa + tile_off(ar[mt], ka));
#pragma unroll
            for (int nt = 0; nt < 2; ++nt) ldsm_x4(b[nt], sb + tile_off(br[nt], kb));
#pragma unroll
            for (int mt = 0; mt < 4; ++mt)
#pragma unroll
                for (int nt = 0; nt < 2; ++nt)
#pragma unroll
                    for (int half = 0; half < 2; ++half)
                        mma_16816(acc[mt][nt * 2 + half], a[mt],
                                  b[nt][half * 2], b[nt][half * 2 + 1]);
        }
    }

    const int rbase = m0 + wm0 + (lane >> 2);
    const int cbase = n0 + wn0 + (lane & 3) * 2;
#pragma unroll
    for (int mt = 0; mt < 4; ++mt) {
#pragma unroll
        for (int nf = 0; nf < 4; ++nf) {
            const int row = rbase + mt * 16;
            const int col = cbase + nf * 8;
            if (col < N) {
                float v0 = acc[mt][nf][0], v1 = acc[mt][nf][1];
                float v2 = acc[mt][nf][2], v3 = acc[mt][nf][3];
                if (EPI == 1) {
                    const float b0 = bias[col], b1 = bias[col + 1];
                    v0 = softplus_f(v0 + b0); v1 = softplus_f(v1 + b1);
                    v2 = softplus_f(v2 + b0); v3 = softplus_f(v3 + b1);
                }
                *(float2*)&Cb[(size_t)row * N + col] = make_float2(v0, v1);
                *(float2*)&Cb[(size_t)(row + 8) * N + col] = make_float2(v2, v3);
            }
        }
    }
}

// ---------------- convert: W[K,N] fp32 -> W^T [Npad, K] fp16 ----------------
__global__ __launch_bounds__(256) void convT_kernel(const float* __restrict__ W,
                                                    __half* __restrict__ out,
                                                    int K, int N) {
    __shared__ float tile[32][33];
    const int k0 = blockIdx.x * 32, n0 = blockIdx.y * 32;
    const int tx = threadIdx.x, ty = threadIdx.y;  // 32 x 8
#pragma unroll
    for (int r = 0; r < 32; r += 8) {
        const int n = n0 + tx;
        tile[ty + r][tx] = (n < N) ? W[(size_t)(k0 + ty + r) * N + n] : 0.f;
    }
    __syncthreads();
#pragma unroll
    for (int r = 0; r < 32; r += 8) {
        const int n = n0 + ty + r, k = k0 + tx;
        out[(size_t)n * K + k] = __float2half_rn(tile[tx][ty + r]);
    }
}

// ---------------- convert: A[M,K] fp32 (lda) -> fp16 [M,K] ------------------
__global__ __launch_bounds__(256) void convA_kernel(const float* __restrict__ A,
                                                    __half* __restrict__ out,
                                                    int K, int lda) {
    const int idx = blockIdx.x * blockDim.x + threadIdx.x;
    const int row = idx / (K / 4);
    const int c4 = (idx - row * (K / 4)) * 4;
    const float4 v = *reinterpret_cast<const float4*>(A + (size_t)row * lda + c4);
    __half2* H = reinterpret_cast<__half2*>(out + (size_t)row * K + c4);
    H[0] = __half2(__float2half_rn(v.x), __float2half_rn(v.y));
    H[1] = __half2(__float2half_rn(v.z), __float2half_rn(v.w));
}

// ---------------- causal depthwise conv (k=4) + SiLU -> fp16 ----------------
__global__ __launch_bounds__(256) void conv_silu_kernel(
    const float* __restrict__ xz, const float* __restrict__ kern,
    const float* __restrict__ kb, __half* __restrict__ xc) {
    const int idx = blockIdx.x * blockDim.x + threadIdx.x;
    const int d4 = idx & (DI / 4 - 1);
    const int row = idx / (DI / 4);
    const int l = row & (LL - 1);
    const int d = d4 * 4;

    float4 acc = *(const float4*)(kb + d);
#pragma unroll
    for (int i = 0; i < 4; ++i) {
        const int ll = l - 3 + i;
        if (ll >= 0) {
            const float4 x4 = *(const float4*)(xz + (size_t)(row - 3 + i) * (2 * DI) + d);
            const float4 k4 = *(const float4*)(kern + i * DI + d);
            acc.x = fmaf(x4.x, k4.x, acc.x);
            acc.y = fmaf(x4.y, k4.y, acc.y);
            acc.z = fmaf(x4.z, k4.z, acc.z);
            acc.w = fmaf(x4.w, k4.w, acc.w);
        }
    }
    acc.x = acc.x * __fdividef(1.f, 1.f + __expf(-acc.x));
    acc.y = acc.y * __fdividef(1.f, 1.f + __expf(-acc.y));
    acc.z = acc.z * __fdividef(1.f, 1.f + __expf(-acc.z));
    acc.w = acc.w * __fdividef(1.f, 1.f + __expf(-acc.w));

    __half2* H = reinterpret_cast<__half2*>(xc + (size_t)row * DI + d);
    H[0] = __half2(__float2half_rn(acc.x), __float2half_rn(acc.y));
    H[1] = __half2(__float2half_rn(acc.z), __float2half_rn(acc.w));
}

// ---------------- split-K reduces (deterministic) ---------------------------
__global__ __launch_bounds__(256) void reduce8_kernel(const float* __restrict__ part,
                                                      float* __restrict__ out) {
    const int i = blockIdx.x * blockDim.x + threadIdx.x;
    if (i < MROWS * NX) {
        float s = 0.f;
#pragma unroll
        for (int c = 0; c < 8; ++c) s += part[(size_t)c * (MROWS * NX) + i];
        out[i] = s;
    }
}
__global__ __launch_bounds__(256) void reduce2_kernel(const float* __restrict__ part,
                                                      float* __restrict__ out) {
    const int i = blockIdx.x * blockDim.x + threadIdx.x;  // float4 index
    const float4 a = ((const float4*)part)[i];
    const float4 b = ((const float4*)(part + (size_t)MROWS * DM))[i];
    ((float4*)out)[i] = make_float4(a.x + b.x, a.y + b.y, a.z + b.z, a.w + b.w);
}

// ---------------- selective scan (fp16 u in, fp16 y out) --------------------
__global__ __launch_bounds__(256) void scan_kernel(
    const __half* __restrict__ xc, const float* __restrict__ xdbl,
    const float* __restrict__ delta, const float* __restrict__ xz,
    const float* __restrict__ A_log, const float* __restrict__ Dskip,
    __half* __restrict__ y) {
    const int w = blockIdx.x * 8 + (threadIdx.x >> 5);
    const int lane = threadIdx.x & 31;
    const int b = w >> 10;
    const int dp = w & 1023;
    const int n = lane & 15;
    const int d = dp * 2 + (lane >> 4);

    const float An = -expf(A_log[d * DS + n]);
    const float Dv = Dskip[d];

    const size_t rb = (size_t)(b << 10);
    const float* __restrict__ dptr = delta + rb * DI + d;
    const __half* __restrict__ uptr = xc + rb * DI + d;
    const float* __restrict__ zptr = xz + rb * (2 * DI) + DI + d;
    const float* __restrict__ bcb = xdbl + rb * NX;
    __half* __restrict__ yp = y + rb * DI + d;

    float st = 0.f;
#pragma unroll 4
    for (int l = 0; l < LL; ++l) {
        const float dl = __ldg(dptr + (size_t)l * DI);
        const float u = __half2float(__ldg(uptr + (size_t)l * DI));
        const float Bn = __ldg(bcb + (size_t)l * NX + DR + n);
        const float Cn = __ldg(bcb + (size_t)l * NX + DR + DS + n);
        const float dA = __expf(dl * An);
        st = fmaf(dA, st, dl * u * Bn);
        float c = st * Cn;
        c += __shfl_xor_sync(0xffffffffu, c, 8);
        c += __shfl_xor_sync(0xffffffffu, c, 4);
        c += __shfl_xor_sync(0xffffffffu, c, 2);
        c += __shfl_xor_sync(0xffffffffu, c, 1);
        if (n == 0) {
            const float zv = __ldg(zptr + (size_t)l * (2 * DI));
            const float yv = fmaf(u, Dv, c) * zv * __fdividef(1.f, 1.f + __expf(-zv));
            yp[(size_t)l * DI] = __float2half_rn(yv);
        }
    }
}

// ---------------- launch ----------------------------------------------------
extern "C" void kernel_launch(void* const* d_in, const int* in_sizes, int n_in,
                              void* d_out, int out_size) {
    (void)in_sizes; (void)n_in; (void)out_size;
    const float* hidden = (const float*)d_in[0];
    const float* Win = (const float*)d_in[1];
    const float* Wx = (const float*)d_in[2];
    const float* Wdt = (const float*)d_in[3];
    const float* dt_bias = (const float*)d_in[4];
    const float* Wout = (const float*)d_in[5];
    const float* dwk = (const float*)d_in[6];
    const float* dwb = (const float*)d_in[7];
    const float* A_log = (const float*)d_in[8];
    const float* Dskip = (const float*)d_in[9];
    float* out = (float*)d_out;

    float *xz, *xdbl, *dlt, *part, *part4;
    cudaGetSymbolAddress((void**)&xz, g_xz);
    cudaGetSymbolAddress((void**)&xdbl, g_xdbl);
    cudaGetSymbolAddress((void**)&dlt, g_delta);
    cudaGetSymbolAddress((void**)&part, g_part);
    cudaGetSymbolAddress((void**)&part4, g_part4);

    __half *WinT, *WxT, *WdtT, *WoutT, *h16, *xc16, *dt16, *y16;
    cudaGetSymbolAddress((void**)&WinT, g_WinT);
    cudaGetSymbolAddress((void**)&WxT, g_WxT);
    cudaGetSymbolAddress((void**)&WdtT, g_WdtT);
    cudaGetSymbolAddress((void**)&WoutT, g_WoutT);
    cudaGetSymbolAddress((void**)&h16, g_h);
    cudaGetSymbolAddress((void**)&xc16, g_xc);
    cudaGetSymbolAddress((void**)&dt16, g_dt);
    cudaGetSymbolAddress((void**)&y16, g_y);

    cudaFuncSetAttribute(mma_gemm<0>, cudaFuncAttributeMaxDynamicSharedMemorySize, GSMEM);
    cudaFuncSetAttribute(mma_gemm<1>, cudaFuncAttributeMaxDynamicSharedMemorySize, GSMEM);

    const dim3 tb(32, 8);

    convT_kernel<<<dim3(DM / 32, 4096 / 32), tb>>>(Win, WinT, DM, 2 * DI);         // 0
    convA_kernel<<<(MROWS * DM / 4) / 256, 256>>>(hidden, h16, DM, DM);            // 1
    convT_kernel<<<dim3(DI / 32, 128 / 32), tb>>>(Wx, WxT, DI, NX);                // 2

    // GEMM1: xz = hidden @ Win  (M=2048, N=4096, K=1024)                           // 3
    mma_gemm<0><<<dim3(4096 / 128, MROWS / 128, 1), 256, GSMEM>>>(
        h16, WinT, xz, 2 * DI, DM, DM / 32, nullptr);

    convT_kernel<<<dim3(DR / 32, DI / 32), tb>>>(Wdt, WdtT, DR, DI);               // 4
    convT_kernel<<<dim3(DI / 32, DM / 32), tb>>>(Wout, WoutT, DI, DM);             // 5

    // conv + silu -> xc fp16                                                       // 6
    conv_silu_kernel<<<(MROWS * DI / 4) / 256, 256>>>(xz, dwk, dwb, xc16);

    // GEMM2: x_dbl = xc @ Wx  (N=96, K=2048), split-K x8 + reduce                  // 7,8
    mma_gemm<0><<<dim3(1, MROWS / 128, 8), 256, GSMEM>>>(
        xc16, WxT, part, NX, DI, (DI / 32) / 8, nullptr);
    reduce8_kernel<<<(MROWS * NX + 255) / 256, 256>>>(part, xdbl);

    // dt slice -> fp16 (K=64, lda=96)                                              // 9
    convA_kernel<<<(MROWS * DR / 4) / 256, 256>>>(xdbl, dt16, DR, NX);

    // GEMM3: delta = softplus(dt @ Wdt + bias)  (N=2048, K=64)                     // 10
    mma_gemm<1><<<dim3(DI / 128, MROWS / 128, 1), 256, GSMEM>>>(
        dt16, WdtT, dlt, DI, DR, DR / 32, dt_bias);

    // selective scan -> y fp16                                                     // 11
    scan_kernel<<<256, 256>>>(xc16, xdbl, dlt, xz, A_log, Dskip, y16);

    // GEMM4: out = y @ Wout  (N=1024, K=2048), split-K x2 + reduce                 // 12,13
    mma_gemm<0><<<dim3(DM / 128, MROWS / 128, 2), 256, GSMEM>>>(
        y16, WoutT, part4, DM, DI, (DI / 32) / 2, nullptr);
    reduce2_kernel<<<(MROWS * DM / 4) / 256, 256>>>(part4, out);
}

// round 13
// speedup vs baseline: 1.9547x; 1.9547x over previous
#include <cuda_runtime.h>
#include <cuda_fp16.h>
#include <cstdint>
#include <math.h>

// Problem constants
#define BB 2
#define LL 1024
#define DM 1024
#define DI 2048
#define DS 16
#define DR 64
#define NX 96          // DR + 2*DS
#define MROWS 2048     // B*L

// ---------------- scratch (device globals; no allocation allowed) -----------
__device__ float g_xz[(size_t)MROWS * 2 * DI];       // 2048 x 4096 fp32
__device__ float g_xdblT[(size_t)96 * MROWS];        // [n, bl] fp32 (rows 64..95 used)
__device__ float g_deltaT[(size_t)DI * MROWS];       // [d, bl] fp32
__device__ float g_part[(size_t)8 * 128 * MROWS];    // split-K partials, GEMM2T
__device__ float g_part4[(size_t)2 * MROWS * DM];    // split-K partials, GEMM4

__device__ __half g_WinT[(size_t)4096 * 1024];
__device__ __half g_WxT[(size_t)128 * 2048];         // N padded 96 -> 128
__device__ __half g_WdtT[(size_t)2048 * 64];
__device__ __half g_WoutT[(size_t)1024 * 2048];
__device__ __half g_h[(size_t)2048 * 1024];
__device__ __half g_xc[(size_t)2048 * 2048];         // conv+silu out [bl, d]
__device__ __half g_xcT[(size_t)2048 * 2048];        // [d, bl]
__device__ __half g_zT[(size_t)2048 * 2048];         // [d, bl] fp16 gate
__device__ __half g_dt[(size_t)2048 * 64];           // [bl, k]
__device__ __half g_yT[(size_t)2048 * 2048];         // scan out [d, bl]
__device__ __half g_y[(size_t)2048 * 2048];          // [bl, d]

// ---------------- helpers ----------------------------------------------------
__device__ __forceinline__ uint32_t smem_u32(const void* p) {
    uint32_t a;
    asm("{ .reg .u64 t; cvta.to.shared.u64 t, %1; cvt.u32.u64 %0, t; }" : "=r"(a) : "l"(p));
    return a;
}
__device__ __forceinline__ void cp_async16(uint32_t dst, const void* src) {
    asm volatile("cp.async.cg.shared.global [%0], [%1], 16;" :: "r"(dst), "l"(src));
}
#define CP_COMMIT() asm volatile("cp.async.commit_group;" ::: "memory")
#define CP_WAIT2()  asm volatile("cp.async.wait_group 2;" ::: "memory")

__device__ __forceinline__ void ldsm_x4(uint32_t* r, uint32_t addr) {
    asm volatile("ldmatrix.sync.aligned.m8n8.x4.shared.b16 {%0,%1,%2,%3}, [%4];"
                 : "=r"(r[0]), "=r"(r[1]), "=r"(r[2]), "=r"(r[3]) : "r"(addr));
}
__device__ __forceinline__ void mma_16816(float* c, const uint32_t* a, uint32_t b0,
                                          uint32_t b1) {
    asm volatile(
        "mma.sync.aligned.m16n8k16.row.col.f32.f16.f16.f32 "
        "{%0,%1,%2,%3}, {%4,%5,%6,%7}, {%8,%9}, {%0,%1,%2,%3};"
        : "+f"(c[0]), "+f"(c[1]), "+f"(c[2]), "+f"(c[3])
        : "r"(a[0]), "r"(a[1]), "r"(a[2]), "r"(a[3]), "r"(b0), "r"(b1));
}

__device__ __forceinline__ float softplus_f(float v) {
    return fmaxf(v, 0.f) + log1pf(__expf(-fabsf(v)));
}

// Swizzled smem byte offset inside a 128x32 fp16 tile (8KB).
__device__ __forceinline__ uint32_t tile_off(int r, int k8) {
    const int prow = r >> 1;
    const int slot = (((r & 1) << 2) | (k8 >> 3)) ^ (prow & 7);
    return (uint32_t)((prow << 7) + (slot << 4));
}

// ---------------- mma.sync GEMM ----------------------------------------------
// C[M,N] = A[M,K] @ B^T[N,K], fp16 operands, fp32 accum.
// EPI: 0 plain, 2 softplus(acc + bias[row]).
// Split-K: gridDim.z chunks K; block z writes C + z*M*N.
#define STAGE_B 16384
#define GSMEM (4 * STAGE_B)

template <int EPI>
__global__ __launch_bounds__(256, 2) void mma_gemm(
    const __half* __restrict__ A, const __half* __restrict__ B,
    float* __restrict__ C, int M, int N, int K, int cpz,
    const float* __restrict__ bias) {
    extern __shared__ __align__(16) char smem[];
    const uint32_t smu = smem_u32(smem);

    const int tid = threadIdx.x;
    const int lane = tid & 31;
    const int wid = tid >> 5;
    const int m0 = blockIdx.y * 128;
    const int n0 = blockIdx.x * 128;
    const int cbeg = blockIdx.z * cpz;
    float* __restrict__ Cb = C + (size_t)blockIdx.z * (size_t)M * (size_t)N;

    const int wm0 = (wid & 1) * 64;
    const int wn0 = (wid >> 1) * 32;

    const int gr0 = tid >> 2, gkc = (tid & 3) * 8;
    const uint32_t d0 = tile_off(gr0, gkc);
    const uint32_t d1 = tile_off(gr0 + 64, gkc);
    const __half* Ag = A + (size_t)(m0 + gr0) * K + gkc;
    const __half* Ag2 = A + (size_t)(m0 + gr0 + 64) * K + gkc;
    const __half* Bg = B + (size_t)(n0 + gr0) * K + gkc;
    const __half* Bg2 = B + (size_t)(n0 + gr0 + 64) * K + gkc;

    auto stage_load = [&](int s, int ck) {
        const int k0 = ck * 32;
        const uint32_t sa = smu + s * STAGE_B;
        const uint32_t sb = sa + 8192;
        cp_async16(sa + d0, Ag + k0);
        cp_async16(sa + d1, Ag2 + k0);
        cp_async16(sb + d0, Bg + k0);
        cp_async16(sb + d1, Bg2 + k0);
    };

    float acc[4][4][4];
#pragma unroll
    for (int i = 0; i < 4; ++i)
#pragma unroll
        for (int j = 0; j < 4; ++j)
#pragma unroll
            for (int q = 0; q < 4; ++q) acc[i][j][q] = 0.f;

#pragma unroll
    for (int p = 0; p < 3; ++p) {
        if (p < cpz) stage_load(p, cbeg + p);
        CP_COMMIT();
    }

    const int lr = lane & 7;
    const int lb1 = (lane >> 3) & 1;
    const int lb2 = lane >> 4;
    const int ar[4] = {wm0 + 0 + lb1 * 8 + lr, wm0 + 16 + lb1 * 8 + lr,
                       wm0 + 32 + lb1 * 8 + lr, wm0 + 48 + lb1 * 8 + lr};
    const int br[2] = {wn0 + 0 + lb2 * 8 + lr, wn0 + 16 + lb2 * 8 + lr};

    for (int j = 0; j < cpz; ++j) {
        const int s = j & 3;
        CP_WAIT2();
        __syncthreads();

        if (j + 3 < cpz) stage_load((j + 3) & 3, cbeg + j + 3);
        CP_COMMIT();

        const uint32_t sa = smu + s * STAGE_B;
        const uint32_t sb = sa + 8192;
#pragma unroll
        for (int kk = 0; kk < 2; ++kk) {
            uint32_t a[4][4], b[2][4];
            const int ka = kk * 16 + lb2 * 8;
            const int kb = kk * 16 + lb1 * 8;
#pragma unroll
            for (int mt = 0; mt < 4; ++mt) ldsm_x4(a[mt], sa + tile_off(ar[mt], ka));
#pragma unroll
            for (int nt = 0; nt < 2; ++nt) ldsm_x4(b[nt], sb + tile_off(br[nt], kb));
#pragma unroll
            for (int mt = 0; mt < 4; ++mt)
#pragma unroll
                for (int nt = 0; nt < 2; ++nt)
#pragma unroll
                    for (int half = 0; half < 2; ++half)
                        mma_16816(acc[mt][nt * 2 + half], a[mt],
                                  b[nt][half * 2], b[nt][half * 2 + 1]);
        }
    }

    const int rbase = m0 + wm0 + (lane >> 2);
    const int cbase = n0 + wn0 + (lane & 3) * 2;
#pragma unroll
    for (int mt = 0; mt < 4; ++mt) {
#pragma unroll
        for (int nf = 0; nf < 4; ++nf) {
            const int row = rbase + mt * 16;
            const int col = cbase + nf * 8;
            if (col < N) {
                float v0 = acc[mt][nf][0], v1 = acc[mt][nf][1];
                float v2 = acc[mt][nf][2], v3 = acc[mt][nf][3];
                if (EPI == 2) {
                    const float b0 = bias[row], b1 = bias[row + 8];
                    v0 = softplus_f(v0 + b0); v1 = softplus_f(v1 + b0);
                    v2 = softplus_f(v2 + b1); v3 = softplus_f(v3 + b1);
                }
                *(float2*)&Cb[(size_t)row * N + col] = make_float2(v0, v1);
                *(float2*)&Cb[(size_t)(row + 8) * N + col] = make_float2(v2, v3);
            }
        }
    }
}

// ---------------- convert: W[K,N] fp32 -> W^T [Npad, K] fp16 ----------------
__global__ __launch_bounds__(256) void convT_kernel(const float* __restrict__ W,
                                                    __half* __restrict__ out,
                                                    int K, int N) {
    __shared__ float tile[32][33];
    const int k0 = blockIdx.x * 32, n0 = blockIdx.y * 32;
    const int tx = threadIdx.x, ty = threadIdx.y;  // 32 x 8
#pragma unroll
    for (int r = 0; r < 32; r += 8) {
        const int n = n0 + tx;
        tile[ty + r][tx] = (n < N) ? W[(size_t)(k0 + ty + r) * N + n] : 0.f;
    }
    __syncthreads();
#pragma unroll
    for (int r = 0; r < 32; r += 8) {
        const int n = n0 + ty + r, k = k0 + tx;
        out[(size_t)n * K + k] = __float2half_rn(tile[tx][ty + r]);
    }
}

// ---------------- convert: A[M,K] fp32 (lda) -> fp16 [M,K] ------------------
__global__ __launch_bounds__(256) void convA_kernel(const float* __restrict__ A,
                                                    __half* __restrict__ out,
                                                    int K, int lda) {
    const int idx = blockIdx.x * blockDim.x + threadIdx.x;
    const int row = idx / (K / 4);
    const int c4 = (idx - row * (K / 4)) * 4;
    const float4 v = *reinterpret_cast<const float4*>(A + (size_t)row * lda + c4);
    __half2* H = reinterpret_cast<__half2*>(out + (size_t)row * K + c4);
    H[0] = __half2(__float2half_rn(v.x), __float2half_rn(v.y));
    H[1] = __half2(__float2half_rn(v.z), __float2half_rn(v.w));
}

// ---------------- transpose: fp16 [R,C] -> fp16 [C,R] -----------------------
__global__ __launch_bounds__(256) void transpose_h2h(const __half* __restrict__ in,
                                                     __half* __restrict__ out,
                                                     int R, int C) {
    __shared__ __half tile[32][33];
    const int r0 = blockIdx.y * 32, c0 = blockIdx.x * 32;
    const int tx = threadIdx.x, ty = threadIdx.y;  // 32 x 8
#pragma unroll
    for (int k = 0; k < 32; k += 8)
        tile[ty + k][tx] = in[(size_t)(r0 + ty + k) * C + c0 + tx];
    __syncthreads();
#pragma unroll
    for (int k = 0; k < 32; k += 8)
        out[(size_t)(c0 + ty + k) * R + r0 + tx] = tile[tx][ty + k];
}

// ------- transpose+convert: fp32 in[R, ld] cols [col0, col0+C) -> fp16 [C,R] -
__global__ __launch_bounds__(256) void transpose_f2h(const float* __restrict__ in,
                                                     __half* __restrict__ out,
                                                     int R, int ldin, int col0,
                                                     int C) {
    __shared__ float tile[32][33];
    const int r0 = blockIdx.y * 32, c0 = blockIdx.x * 32;
    const int tx = threadIdx.x, ty = threadIdx.y;
#pragma unroll
    for (int k = 0; k < 32; k += 8)
        tile[ty + k][tx] = in[(size_t)(r0 + ty + k) * ldin + col0 + c0 + tx];
    __syncthreads();
#pragma unroll
    for (int k = 0; k < 32; k += 8)
        out[(size_t)(c0 + ty + k) * R + r0 + tx] = __float2half_rn(tile[tx][ty + k]);
}

// ---------------- causal depthwise conv (k=4) + SiLU -> fp16 [bl, d] --------
__global__ __launch_bounds__(256) void conv_silu_kernel(
    const float* __restrict__ xz, const float* __restrict__ kern,
    const float* __restrict__ kb, __half* __restrict__ xc) {
    const int idx = blockIdx.x * blockDim.x + threadIdx.x;
    const int d4 = idx & (DI / 4 - 1);
    const int row = idx / (DI / 4);
    const int l = row & (LL - 1);
    const int d = d4 * 4;

    float4 acc = *(const float4*)(kb + d);
#pragma unroll
    for (int i = 0; i < 4; ++i) {
        const int ll = l - 3 + i;
        if (ll >= 0) {
            const float4 x4 = *(const float4*)(xz + (size_t)(row - 3 + i) * (2 * DI) + d);
            const float4 k4 = *(const float4*)(kern + i * DI + d);
            acc.x = fmaf(x4.x, k4.x, acc.x);
            acc.y = fmaf(x4.y, k4.y, acc.y);
            acc.z = fmaf(x4.z, k4.z, acc.z);
            acc.w = fmaf(x4.w, k4.w, acc.w);
        }
    }
    acc.x = acc.x * __fdividef(1.f, 1.f + __expf(-acc.x));
    acc.y = acc.y * __fdividef(1.f, 1.f + __expf(-acc.y));
    acc.z = acc.z * __fdividef(1.f, 1.f + __expf(-acc.z));
    acc.w = acc.w * __fdividef(1.f, 1.f + __expf(-acc.w));

    __half2* H = reinterpret_cast<__half2*>(xc + (size_t)row * DI + d);
    H[0] = __half2(__float2half_rn(acc.x), __float2half_rn(acc.y));
    H[1] = __half2(__float2half_rn(acc.z), __float2half_rn(acc.w));
}

// ---------------- split-K reduce for GEMM2T + fused dt fp16 transpose -------
__global__ __launch_bounds__(256) void reduce8T_kernel(const float* __restrict__ part,
                                                       float* __restrict__ xdblT,
                                                       __half* __restrict__ dt16) {
    const int idx = blockIdx.x * blockDim.x + threadIdx.x;  // 96*512
    if (idx >= 96 * (MROWS / 4)) return;
    const int r = idx >> 9;
    const int c4 = (idx & 511) * 4;
    const float* p = part + (size_t)r * MROWS + c4;
    float4 s = make_float4(0.f, 0.f, 0.f, 0.f);
#pragma unroll
    for (int z = 0; z < 8; ++z) {
        const float4 v = *(const float4*)(p + (size_t)z * 128 * MROWS);
        s.x += v.x; s.y += v.y; s.z += v.z; s.w += v.w;
    }
    if (r < 64) {
        dt16[(size_t)(c4 + 0) * DR + r] = __float2half_rn(s.x);
        dt16[(size_t)(c4 + 1) * DR + r] = __float2half_rn(s.y);
        dt16[(size_t)(c4 + 2) * DR + r] = __float2half_rn(s.z);
        dt16[(size_t)(c4 + 3) * DR + r] = __float2half_rn(s.w);
    } else {
        *(float4*)(xdblT + (size_t)r * MROWS + c4) = s;
    }
}

// ---------------- split-K reduce for GEMM4 ----------------------------------
__global__ __launch_bounds__(256) void reduce2_kernel(const float* __restrict__ part,
                                                      float* __restrict__ out) {
    const int i = blockIdx.x * blockDim.x + threadIdx.x;
    const float4 a = ((const float4*)part)[i];
    const float4 b = ((const float4*)(part + (size_t)MROWS * DM))[i];
    ((float4*)out)[i] = make_float4(a.x + b.x, a.y + b.y, a.z + b.z, a.w + b.w);
}

// ---------------- selective scan on transposed operands ---------------------
// All inputs [d, bl] time-contiguous; 4 timesteps per vector load; register
// prefetch pipeline. warp = 2 channels x 16 states; 2048 warps.
__device__ __forceinline__ void unpack_h4(uint2 v, float* o) {
    const __half2 p0 = *reinterpret_cast<__half2*>(&v.x);
    const __half2 p1 = *reinterpret_cast<__half2*>(&v.y);
    o[0] = __low2float(p0); o[1] = __high2float(p0);
    o[2] = __low2float(p1); o[3] = __high2float(p1);
}

__global__ __launch_bounds__(256) void scanT_kernel(
    const __half* __restrict__ xcT, const float* __restrict__ xdblT,
    const float* __restrict__ deltaT, const __half* __restrict__ zT,
    const float* __restrict__ A_log, const float* __restrict__ Dskip,
    __half* __restrict__ yT) {
    const int w = blockIdx.x * 8 + (threadIdx.x >> 5);
    const int lane = threadIdx.x & 31;
    const int b = w >> 10;
    const int dp = w & 1023;
    const int n = lane & 15;
    const int d = dp * 2 + (lane >> 4);
    const bool lead = (n == 0);

    const float An = -expf(A_log[d * DS + n]);
    const float Dv = Dskip[d];

    const int base = b << 10;  // b*1024
    const float* __restrict__ dT = deltaT + (size_t)d * MROWS + base;
    const __half* __restrict__ uT = xcT + (size_t)d * MROWS + base;
    const __half* __restrict__ zp = zT + (size_t)d * MROWS + base;
    const float* __restrict__ BT = xdblT + (size_t)(64 + n) * MROWS + base;
    const float* __restrict__ CT = xdblT + (size_t)(80 + n) * MROWS + base;
    __half* __restrict__ yp = yT + (size_t)d * MROWS + base;

    // prologue loads (group 0)
    float4 dl4 = *(const float4*)dT;
    uint2 uu = *(const uint2*)uT;
    float4 B4 = *(const float4*)BT;
    float4 C4 = *(const float4*)CT;
    uint2 zz = make_uint2(0u, 0u);
    if (lead) zz = *(const uint2*)zp;

    float st = 0.f;
    for (int l0 = 0; l0 < LL; l0 += 4) {
        // prefetch next group
        float4 dl4n = dl4; uint2 uun = uu; float4 B4n = B4, C4n = C4; uint2 zzn = zz;
        if (l0 + 4 < LL) {
            dl4n = *(const float4*)(dT + l0 + 4);
            uun = *(const uint2*)(uT + l0 + 4);
            B4n = *(const float4*)(BT + l0 + 4);
            C4n = *(const float4*)(CT + l0 + 4);
            if (lead) zzn = *(const uint2*)(zp + l0 + 4);
        }

        const float dls[4] = {dl4.x, dl4.y, dl4.z, dl4.w};
        const float Bs[4] = {B4.x, B4.y, B4.z, B4.w};
        const float Cs[4] = {C4.x, C4.y, C4.z, C4.w};
        float us[4]; unpack_h4(uu, us);
        float zs[4]; unpack_h4(zz, zs);

        float ys[4];
#pragma unroll
        for (int j = 0; j < 4; ++j) {
            const float dA = __expf(dls[j] * An);
            st = fmaf(dA, st, dls[j] * us[j] * Bs[j]);
            float c = st * Cs[j];
            c += __shfl_xor_sync(0xffffffffu, c, 8);
            c += __shfl_xor_sync(0xffffffffu, c, 4);
            c += __shfl_xor_sync(0xffffffffu, c, 2);
            c += __shfl_xor_sync(0xffffffffu, c, 1);
            const float zv = zs[j];
            ys[j] = fmaf(us[j], Dv, c) * zv * __fdividef(1.f, 1.f + __expf(-zv));
        }
        if (lead) {
            const __half2 o0 = __floats2half2_rn(ys[0], ys[1]);
            const __half2 o1 = __floats2half2_rn(ys[2], ys[3]);
            uint2 ov;
            ov.x = *reinterpret_cast<const uint32_t*>(&o0);
            ov.y = *reinterpret_cast<const uint32_t*>(&o1);
            *(uint2*)(yp + l0) = ov;
        }
        dl4 = dl4n; uu = uun; B4 = B4n; C4 = C4n; zz = zzn;
    }
}

// ---------------- launch ----------------------------------------------------
extern "C" void kernel_launch(void* const* d_in, const int* in_sizes, int n_in,
                              void* d_out, int out_size) {
    (void)in_sizes; (void)n_in; (void)out_size;
    const float* hidden = (const float*)d_in[0];
    const float* Win = (const float*)d_in[1];
    const float* Wx = (const float*)d_in[2];
    const float* Wdt = (const float*)d_in[3];
    const float* dt_bias = (const float*)d_in[4];
    const float* Wout = (const float*)d_in[5];
    const float* dwk = (const float*)d_in[6];
    const float* dwb = (const float*)d_in[7];
    const float* A_log = (const float*)d_in[8];
    const float* Dskip = (const float*)d_in[9];
    float* out = (float*)d_out;

    float *xz, *xdblT, *deltaT, *part, *part4;
    cudaGetSymbolAddress((void**)&xz, g_xz);
    cudaGetSymbolAddress((void**)&xdblT, g_xdblT);
    cudaGetSymbolAddress((void**)&deltaT, g_deltaT);
    cudaGetSymbolAddress((void**)&part, g_part);
    cudaGetSymbolAddress((void**)&part4, g_part4);

    __half *WinT, *WxT, *WdtT, *WoutT, *h16, *xc16, *xcT, *zT, *dt16, *yT, *y16;
    cudaGetSymbolAddress((void**)&WinT, g_WinT);
    cudaGetSymbolAddress((void**)&WxT, g_WxT);
    cudaGetSymbolAddress((void**)&WdtT, g_WdtT);
    cudaGetSymbolAddress((void**)&WoutT, g_WoutT);
    cudaGetSymbolAddress((void**)&h16, g_h);
    cudaGetSymbolAddress((void**)&xc16, g_xc);
    cudaGetSymbolAddress((void**)&xcT, g_xcT);
    cudaGetSymbolAddress((void**)&zT, g_zT);
    cudaGetSymbolAddress((void**)&dt16, g_dt);
    cudaGetSymbolAddress((void**)&yT, g_yT);
    cudaGetSymbolAddress((void**)&y16, g_y);

    cudaFuncSetAttribute(mma_gemm<0>, cudaFuncAttributeMaxDynamicSharedMemorySize, GSMEM);
    cudaFuncSetAttribute(mma_gemm<2>, cudaFuncAttributeMaxDynamicSharedMemorySize, GSMEM);

    const dim3 tb(32, 8);

    convT_kernel<<<dim3(DM / 32, 4096 / 32), tb>>>(Win, WinT, DM, 2 * DI);         // 0
    convA_kernel<<<(MROWS * DM / 4) / 256, 256>>>(hidden, h16, DM, DM);            // 1
    convT_kernel<<<dim3(DI / 32, 128 / 32), tb>>>(Wx, WxT, DI, NX);                // 2

    // GEMM1: xz = hidden @ Win  (M=2048, N=4096, K=1024)   [profiled launch]      // 3
    mma_gemm<0><<<dim3(4096 / 128, MROWS / 128, 1), 256, GSMEM>>>(
        h16, WinT, xz, MROWS, 2 * DI, DM, DM / 32, nullptr);

    convT_kernel<<<dim3(DR / 32, DI / 32), tb>>>(Wdt, WdtT, DR, DI);               // 4
    convT_kernel<<<dim3(DI / 32, DM / 32), tb>>>(Wout, WoutT, DI, DM);             // 5

    // conv + silu -> xc16 [bl, d]                                                  // 6
    conv_silu_kernel<<<(MROWS * DI / 4) / 256, 256>>>(xz, dwk, dwb, xc16);

    // transposes for the scan                                                      // 7, 8
    transpose_h2h<<<dim3(DI / 32, MROWS / 32), tb>>>(xc16, xcT, MROWS, DI);
    transpose_f2h<<<dim3(DI / 32, MROWS / 32), tb>>>(xz, zT, MROWS, 2 * DI, DI, DI);

    // GEMM2T: xdblT = Wx^T-side GEMM  (M=128, N=2048(bl), K=2048), split-K x8     // 9, 10
    mma_gemm<0><<<dim3(MROWS / 128, 1, 8), 256, GSMEM>>>(
        WxT, xc16, part, 128, MROWS, DI, (DI / 32) / 8, nullptr);
    reduce8T_kernel<<<(96 * (MROWS / 4) + 255) / 256, 256>>>(part, xdblT, dt16);

    // GEMM3T: deltaT[d, bl] = softplus(Wdt^T @ dt^T + bias[d])  (M=2048, N=2048, K=64)  // 11
    mma_gemm<2><<<dim3(MROWS / 128, DI / 128, 1), 256, GSMEM>>>(
        WdtT, dt16, deltaT, DI, MROWS, DR, DR / 32, dt_bias);

    // selective scan on [d, bl] operands -> yT                                     // 12
    scanT_kernel<<<256, 256>>>(xcT, xdblT, deltaT, zT, A_log, Dskip, yT);

    // yT -> y16 [bl, d]                                                            // 13
    transpose_h2h<<<dim3(MROWS / 32, DI / 32), tb>>>(yT, y16, DI, MROWS);

    // GEMM4: out = y @ Wout  (M=2048, N=1024, K=2048), split-K x2 + reduce         // 14, 15
    mma_gemm<0><<<dim3(DM / 128, MROWS / 128, 2), 256, GSMEM>>>(
        y16, WoutT, part4, MROWS, DM, DI, (DI / 32) / 2, nullptr);
    reduce2_kernel<<<(MROWS * DM / 4) / 256, 256>>>(part4, out);
}

// round 16
// speedup vs baseline: 2.0086x; 1.0276x over previous
#include <cuda_runtime.h>
#include <cuda_fp16.h>
#include <cstdint>
#include <math.h>

// Problem constants
#define BB 2
#define LL 1024
#define DM 1024
#define DI 2048
#define DS 16
#define DR 64
#define NX 96          // DR + 2*DS
#define MROWS 2048     // B*L

// ---------------- scratch (device globals; no allocation allowed) -----------
__device__ __half g_xz16[(size_t)MROWS * 2 * DI];    // GEMM1 out, fp16 [bl, 4096]
__device__ float g_xdblT[(size_t)96 * MROWS];        // [n, bl] fp32 (rows 64..95 used)
__device__ float g_deltaT[(size_t)DI * MROWS];       // [d, bl] fp32
__device__ float g_part[(size_t)8 * 128 * MROWS];    // split-K partials, GEMM2T
__device__ float g_part4[(size_t)2 * MROWS * DM];    // split-K partials, GEMM4

__device__ __half g_WinT[(size_t)4096 * 1024];
__device__ __half g_WxT[(size_t)128 * 2048];         // N padded 96 -> 128
__device__ __half g_WdtT[(size_t)2048 * 64];
__device__ __half g_WoutT[(size_t)1024 * 2048];
__device__ __half g_h[(size_t)2048 * 1024];
__device__ __half g_xc[(size_t)2048 * 2048];         // conv+silu out [bl, d]
__device__ __half g_xcT[(size_t)2048 * 2048];        // [d, bl]
__device__ __half g_zT[(size_t)2048 * 2048];         // [d, bl] fp16 gate
__device__ __half g_dt[(size_t)2048 * 64];           // [bl, k]
__device__ __half g_yT[(size_t)2048 * 2048];         // scan out [d, bl]
__device__ __half g_y[(size_t)2048 * 2048];          // [bl, d]

// ---------------- helpers ----------------------------------------------------
__device__ __forceinline__ uint32_t smem_u32(const void* p) {
    uint32_t a;
    asm("{ .reg .u64 t; cvta.to.shared.u64 t, %1; cvt.u32.u64 %0, t; }" : "=r"(a) : "l"(p));
    return a;
}
__device__ __forceinline__ void cp_async16(uint32_t dst, const void* src) {
    asm volatile("cp.async.cg.shared.global [%0], [%1], 16;" :: "r"(dst), "l"(src));
}
#define CP_COMMIT() asm volatile("cp.async.commit_group;" ::: "memory")
#define CP_WAIT2()  asm volatile("cp.async.wait_group 2;" ::: "memory")

__device__ __forceinline__ void ldsm_x4(uint32_t* r, uint32_t addr) {
    asm volatile("ldmatrix.sync.aligned.m8n8.x4.shared.b16 {%0,%1,%2,%3}, [%4];"
                 : "=r"(r[0]), "=r"(r[1]), "=r"(r[2]), "=r"(r[3]) : "r"(addr));
}
__device__ __forceinline__ void mma_16816(float* c, const uint32_t* a, uint32_t b0,
                                          uint32_t b1) {
    asm volatile(
        "mma.sync.aligned.m16n8k16.row.col.f32.f16.f16.f32 "
        "{%0,%1,%2,%3}, {%4,%5,%6,%7}, {%8,%9}, {%0,%1,%2,%3};"
        : "+f"(c[0]), "+f"(c[1]), "+f"(c[2]), "+f"(c[3])
        : "r"(a[0]), "r"(a[1]), "r"(a[2]), "r"(a[3]), "r"(b0), "r"(b1));
}

__device__ __forceinline__ float softplus_f(float v) {
    return fmaxf(v, 0.f) + log1pf(__expf(-fabsf(v)));
}

// Swizzled smem byte offset inside a 128x32 fp16 tile (8KB).
__device__ __forceinline__ uint32_t tile_off(int r, int k8) {
    const int prow = r >> 1;
    const int slot = (((r & 1) << 2) | (k8 >> 3)) ^ (prow & 7);
    return (uint32_t)((prow << 7) + (slot << 4));
}

// ---------------- mma.sync GEMM ----------------------------------------------
// C[M,N] = A[M,K] @ B^T[N,K], fp16 operands, fp32 accum.
// EPI: 0 plain fp32, 2 softplus(acc + bias[row]) fp32, 3 fp16 store.
// Split-K: gridDim.z chunks K; block z writes C + z*M*N.
#define STAGE_B 16384
#define GSMEM (4 * STAGE_B)

template <int EPI>
__global__ __launch_bounds__(256, 2) void mma_gemm(
    const __half* __restrict__ A, const __half* __restrict__ B,
    float* __restrict__ C, int M, int N, int K, int cpz,
    const float* __restrict__ bias) {
    extern __shared__ __align__(16) char smem[];
    const uint32_t smu = smem_u32(smem);

    const int tid = threadIdx.x;
    const int lane = tid & 31;
    const int wid = tid >> 5;
    const int m0 = blockIdx.y * 128;
    const int n0 = blockIdx.x * 128;
    const int cbeg = blockIdx.z * cpz;
    float* __restrict__ Cb = C + (size_t)blockIdx.z * (size_t)M * (size_t)N;

    const int wm0 = (wid & 1) * 64;
    const int wn0 = (wid >> 1) * 32;

    const int gr0 = tid >> 2, gkc = (tid & 3) * 8;
    const uint32_t d0 = tile_off(gr0, gkc);
    const uint32_t d1 = tile_off(gr0 + 64, gkc);
    const __half* Ag = A + (size_t)(m0 + gr0) * K + gkc;
    const __half* Ag2 = A + (size_t)(m0 + gr0 + 64) * K + gkc;
    const __half* Bg = B + (size_t)(n0 + gr0) * K + gkc;
    const __half* Bg2 = B + (size_t)(n0 + gr0 + 64) * K + gkc;

    auto stage_load = [&](int s, int ck) {
        const int k0 = ck * 32;
        const uint32_t sa = smu + s * STAGE_B;
        const uint32_t sb = sa + 8192;
        cp_async16(sa + d0, Ag + k0);
        cp_async16(sa + d1, Ag2 + k0);
        cp_async16(sb + d0, Bg + k0);
        cp_async16(sb + d1, Bg2 + k0);
    };

    float acc[4][4][4];
#pragma unroll
    for (int i = 0; i < 4; ++i)
#pragma unroll
        for (int j = 0; j < 4; ++j)
#pragma unroll
            for (int q = 0; q < 4; ++q) acc[i][j][q] = 0.f;

#pragma unroll
    for (int p = 0; p < 3; ++p) {
        if (p < cpz) stage_load(p, cbeg + p);
        CP_COMMIT();
    }

    const int lr = lane & 7;
    const int lb1 = (lane >> 3) & 1;
    const int lb2 = lane >> 4;
    const int ar[4] = {wm0 + 0 + lb1 * 8 + lr, wm0 + 16 + lb1 * 8 + lr,
                       wm0 + 32 + lb1 * 8 + lr, wm0 + 48 + lb1 * 8 + lr};
    const int br[2] = {wn0 + 0 + lb2 * 8 + lr, wn0 + 16 + lb2 * 8 + lr};

    for (int j = 0; j < cpz; ++j) {
        const int s = j & 3;
        CP_WAIT2();
        __syncthreads();

        if (j + 3 < cpz) stage_load((j + 3) & 3, cbeg + j + 3);
        CP_COMMIT();

        const uint32_t sa = smu + s * STAGE_B;
        const uint32_t sb = sa + 8192;
#pragma unroll
        for (int kk = 0; kk < 2; ++kk) {
            uint32_t a[4][4], b[2][4];
            const int ka = kk * 16 + lb2 * 8;
            const int kb = kk * 16 + lb1 * 8;
#pragma unroll
            for (int mt = 0; mt < 4; ++mt) ldsm_x4(a[mt], sa + tile_off(ar[mt], ka));
#pragma unroll
            for (int nt = 0; nt < 2; ++nt) ldsm_x4(b[nt], sb + tile_off(br[nt], kb));
#pragma unroll
            for (int mt = 0; mt < 4; ++mt)
#pragma unroll
                for (int nt = 0; nt < 2; ++nt)
#pragma unroll
                    for (int half = 0; half < 2; ++half)
                        mma_16816(acc[mt][nt * 2 + half], a[mt],
                                  b[nt][half * 2], b[nt][half * 2 + 1]);
        }
    }

    const int rbase = m0 + wm0 + (lane >> 2);
    const int cbase = n0 + wn0 + (lane & 3) * 2;
#pragma unroll
    for (int mt = 0; mt < 4; ++mt) {
#pragma unroll
        for (int nf = 0; nf < 4; ++nf) {
            const int row = rbase + mt * 16;
            const int col = cbase + nf * 8;
            if (col < N) {
                float v0 = acc[mt][nf][0], v1 = acc[mt][nf][1];
                float v2 = acc[mt][nf][2], v3 = acc[mt][nf][3];
                if (EPI == 2) {
                    const float b0 = bias[row], b1 = bias[row + 8];
                    v0 = softplus_f(v0 + b0); v1 = softplus_f(v1 + b0);
                    v2 = softplus_f(v2 + b1); v3 = softplus_f(v3 + b1);
                }
                if (EPI == 3) {
                    __half* C16 = (__half*)C;
                    *(__half2*)&C16[(size_t)row * N + col] =
                        __floats2half2_rn(v0, v1);
                    *(__half2*)&C16[(size_t)(row + 8) * N + col] =
                        __floats2half2_rn(v2, v3);
                } else {
                    *(float2*)&Cb[(size_t)row * N + col] = make_float2(v0, v1);
                    *(float2*)&Cb[(size_t)(row + 8) * N + col] = make_float2(v2, v3);
                }
            }
        }
    }
}

// ---------------- batched weight transpose: all 4 W -> W^T fp16 -------------
__device__ __forceinline__ void convT_tile(const float* __restrict__ W,
                                           __half* __restrict__ out,
                                           int K, int N, int k0, int n0,
                                           int tx, int ty) {
    __shared__ float tile[32][33];
#pragma unroll
    for (int r = 0; r < 32; r += 8) {
        const int n = n0 + tx;
        tile[ty + r][tx] = (n < N) ? W[(size_t)(k0 + ty + r) * N + n] : 0.f;
    }
    __syncthreads();
#pragma unroll
    for (int r = 0; r < 32; r += 8) {
        const int n = n0 + ty + r, k = k0 + tx;
        out[(size_t)n * K + k] = __float2half_rn(tile[tx][ty + r]);
    }
}

__global__ __launch_bounds__(256) void convT_all(
    const float* __restrict__ Win, __half* __restrict__ WinT,
    const float* __restrict__ Wx, __half* __restrict__ WxT,
    const float* __restrict__ Wdt, __half* __restrict__ WdtT,
    const float* __restrict__ Wout, __half* __restrict__ WoutT) {
    const int bid = blockIdx.x;
    const int tx = threadIdx.x, ty = threadIdx.y;
    if (bid < 4096) {               // Win: K=1024 (32 kt), Npad=4096 (128 nt)
        convT_tile(Win, WinT, 1024, 4096, (bid & 31) * 32, (bid >> 5) * 32, tx, ty);
    } else if (bid < 4352) {        // Wx: K=2048 (64 kt), N=96, Npad=128 (4 nt)
        const int b = bid - 4096;
        convT_tile(Wx, WxT, 2048, 96, (b & 63) * 32, (b >> 6) * 32, tx, ty);
    } else if (bid < 4480) {        // Wdt: K=64 (2 kt), N=2048 (64 nt)
        const int b = bid - 4352;
        convT_tile(Wdt, WdtT, 64, 2048, (b & 1) * 32, (b >> 1) * 32, tx, ty);
    } else {                        // Wout: K=2048 (64 kt), N=1024 (32 nt)
        const int b = bid - 4480;
        convT_tile(Wout, WoutT, 2048, 1024, (b & 63) * 32, (b >> 6) * 32, tx, ty);
    }
}
#define CONVT_ALL_BLOCKS 6528

// ---------------- convert: A[M,K] fp32 (lda) -> fp16 [M,K] ------------------
__global__ __launch_bounds__(256) void convA_kernel(const float* __restrict__ A,
                                                    __half* __restrict__ out,
                                                    int K, int lda) {
    const int idx = blockIdx.x * blockDim.x + threadIdx.x;
    const int row = idx / (K / 4);
    const int c4 = (idx - row * (K / 4)) * 4;
    const float4 v = *reinterpret_cast<const float4*>(A + (size_t)row * lda + c4);
    __half2* H = reinterpret_cast<__half2*>(out + (size_t)row * K + c4);
    H[0] = __half2(__float2half_rn(v.x), __float2half_rn(v.y));
    H[1] = __half2(__float2half_rn(v.z), __float2half_rn(v.w));
}

// ---------------- transpose: fp16 [R,C] -> fp16 [C,R] -----------------------
__global__ __launch_bounds__(256) void transpose_h2h(const __half* __restrict__ in,
                                                     __half* __restrict__ out,
                                                     int R, int C) {
    __shared__ __half tile[32][33];
    const int r0 = blockIdx.y * 32, c0 = blockIdx.x * 32;
    const int tx = threadIdx.x, ty = threadIdx.y;  // 32 x 8
#pragma unroll
    for (int k = 0; k < 32; k += 8)
        tile[ty + k][tx] = in[(size_t)(r0 + ty + k) * C + c0 + tx];
    __syncthreads();
#pragma unroll
    for (int k = 0; k < 32; k += 8)
        out[(size_t)(c0 + ty + k) * R + r0 + tx] = tile[tx][ty + k];
}

// ---------------- fused: conv(k=4)+SiLU from fp16 xz -> xc16, xcT, zT -------
__global__ __launch_bounds__(256) void conv_fuse_kernel(
    const __half* __restrict__ xz16, const float* __restrict__ kern,
    const float* __restrict__ kb, __half* __restrict__ xc,
    __half* __restrict__ xcT, __half* __restrict__ zT) {
    __shared__ float xs[35][33];
    __shared__ float zs[32][33];
    __shared__ __half hs[32][33];
    const int bl0 = blockIdx.y * 32;
    const int d0 = blockIdx.x * 32;
    const int tx = threadIdx.x, ty = threadIdx.y;  // 32 x 8
    const int lbase = bl0 & (LL - 1);

    // x history rows bl0-3 .. bl0+31 (zero across batch/sequence start)
    for (int r = ty; r < 35; r += 8) {
        const int lloc = lbase - 3 + r;
        xs[r][tx] = (lloc >= 0)
            ? __half2float(xz16[(size_t)(bl0 - 3 + r) * (2 * DI) + d0 + tx])
            : 0.f;
    }
#pragma unroll
    for (int r = ty; r < 32; r += 8)
        zs[r][tx] = __half2float(xz16[(size_t)(bl0 + r) * (2 * DI) + DI + d0 + tx]);
    __syncthreads();

    const float k0w = kern[0 * DI + d0 + tx];
    const float k1w = kern[1 * DI + d0 + tx];
    const float k2w = kern[2 * DI + d0 + tx];
    const float k3w = kern[3 * DI + d0 + tx];
    const float bw = kb[d0 + tx];
#pragma unroll
    for (int q = 0; q < 4; ++q) {
        const int r = ty + q * 8;
        float acc = bw;
        acc = fmaf(xs[r + 0][tx], k0w, acc);
        acc = fmaf(xs[r + 1][tx], k1w, acc);
        acc = fmaf(xs[r + 2][tx], k2w, acc);
        acc = fmaf(xs[r + 3][tx], k3w, acc);
        acc = acc * __fdividef(1.f, 1.f + __expf(-acc));
        const __half h = __float2half_rn(acc);
        hs[r][tx] = h;
        xc[(size_t)(bl0 + r) * DI + d0 + tx] = h;
    }
    __syncthreads();
#pragma unroll
    for (int q = 0; q < 4; ++q) {
        const int c = ty + q * 8;
        xcT[(size_t)(d0 + c) * MROWS + bl0 + tx] = hs[tx][c];
        zT[(size_t)(d0 + c) * MROWS + bl0 + tx] = __float2half_rn(zs[tx][c]);
    }
}

// ---------------- split-K reduce for GEMM2T + fused dt fp16 transpose -------
__global__ __launch_bounds__(256) void reduce8T_kernel(const float* __restrict__ part,
                                                       float* __restrict__ xdblT,
                                                       __half* __restrict__ dt16) {
    const int idx = blockIdx.x * blockDim.x + threadIdx.x;  // 96*512
    if (idx >= 96 * (MROWS / 4)) return;
    const int r = idx >> 9;
    const int c4 = (idx & 511) * 4;
    const float* p = part + (size_t)r * MROWS + c4;
    float4 s = make_float4(0.f, 0.f, 0.f, 0.f);
#pragma unroll
    for (int z = 0; z < 8; ++z) {
        const float4 v = *(const float4*)(p + (size_t)z * 128 * MROWS);
        s.x += v.x; s.y += v.y; s.z += v.z; s.w += v.w;
    }
    if (r < 64) {
        dt16[(size_t)(c4 + 0) * DR + r] = __float2half_rn(s.x);
        dt16[(size_t)(c4 + 1) * DR + r] = __float2half_rn(s.y);
        dt16[(size_t)(c4 + 2) * DR + r] = __float2half_rn(s.z);
        dt16[(size_t)(c4 + 3) * DR + r] = __float2half_rn(s.w);
    } else {
        *(float4*)(xdblT + (size_t)r * MROWS + c4) = s;
    }
}

// ---------------- split-K reduce for GEMM4 ----------------------------------
__global__ __launch_bounds__(256) void reduce2_kernel(const float* __restrict__ part,
                                                      float* __restrict__ out) {
    const int i = blockIdx.x * blockDim.x + threadIdx.x;
    const float4 a = ((const float4*)part)[i];
    const float4 b = ((const float4*)(part + (size_t)MROWS * DM))[i];
    ((float4*)out)[i] = make_float4(a.x + b.x, a.y + b.y, a.z + b.z, a.w + b.w);
}

// ---------------- selective scan on transposed operands ---------------------
__device__ __forceinline__ void unpack_h4(uint2 v, float* o) {
    const __half2 p0 = *reinterpret_cast<__half2*>(&v.x);
    const __half2 p1 = *reinterpret_cast<__half2*>(&v.y);
    o[0] = __low2float(p0); o[1] = __high2float(p0);
    o[2] = __low2float(p1); o[3] = __high2float(p1);
}

__global__ __launch_bounds__(256) void scanT_kernel(
    const __half* __restrict__ xcT, const float* __restrict__ xdblT,
    const float* __restrict__ deltaT, const __half* __restrict__ zT,
    const float* __restrict__ A_log, const float* __restrict__ Dskip,
    __half* __restrict__ yT) {
    const int w = blockIdx.x * 8 + (threadIdx.x >> 5);
    const int lane = threadIdx.x & 31;
    const int b = w >> 10;
    const int dp = w & 1023;
    const int n = lane & 15;
    const int d = dp * 2 + (lane >> 4);
    const bool lead = (n == 0);

    const float An = -expf(A_log[d * DS + n]);
    const float Dv = Dskip[d];

    const int base = b << 10;
    const float* __restrict__ dT = deltaT + (size_t)d * MROWS + base;
    const __half* __restrict__ uT = xcT + (size_t)d * MROWS + base;
    const __half* __restrict__ zp = zT + (size_t)d * MROWS + base;
    const float* __restrict__ BT = xdblT + (size_t)(64 + n) * MROWS + base;
    const float* __restrict__ CT = xdblT + (size_t)(80 + n) * MROWS + base;
    __half* __restrict__ yp = yT + (size_t)d * MROWS + base;

    float4 dl4 = *(const float4*)dT;
    uint2 uu = *(const uint2*)uT;
    float4 B4 = *(const float4*)BT;
    float4 C4 = *(const float4*)CT;
    uint2 zz = make_uint2(0u, 0u);
    if (lead) zz = *(const uint2*)zp;

    float st = 0.f;
    for (int l0 = 0; l0 < LL; l0 += 4) {
        float4 dl4n = dl4; uint2 uun = uu; float4 B4n = B4, C4n = C4; uint2 zzn = zz;
        if (l0 + 4 < LL) {
            dl4n = *(const float4*)(dT + l0 + 4);
            uun = *(const uint2*)(uT + l0 + 4);
            B4n = *(const float4*)(BT + l0 + 4);
            C4n = *(const float4*)(CT + l0 + 4);
            if (lead) zzn = *(const uint2*)(zp + l0 + 4);
        }

        const float dls[4] = {dl4.x, dl4.y, dl4.z, dl4.w};
        const float Bs[4] = {B4.x, B4.y, B4.z, B4.w};
        const float Cs[4] = {C4.x, C4.y, C4.z, C4.w};
        float us[4]; unpack_h4(uu, us);
        float zs[4]; unpack_h4(zz, zs);

        float ys[4];
#pragma unroll
        for (int j = 0; j < 4; ++j) {
            const float dA = __expf(dls[j] * An);
            st = fmaf(dA, st, dls[j] * us[j] * Bs[j]);
            float c = st * Cs[j];
            c += __shfl_xor_sync(0xffffffffu, c, 8);
            c += __shfl_xor_sync(0xffffffffu, c, 4);
            c += __shfl_xor_sync(0xffffffffu, c, 2);
            c += __shfl_xor_sync(0xffffffffu, c, 1);
            const float zv = zs[j];
            ys[j] = fmaf(us[j], Dv, c) * zv * __fdividef(1.f, 1.f + __expf(-zv));
        }
        if (lead) {
            const __half2 o0 = __floats2half2_rn(ys[0], ys[1]);
            const __half2 o1 = __floats2half2_rn(ys[2], ys[3]);
            uint2 ov;
            ov.x = *reinterpret_cast<const uint32_t*>(&o0);
            ov.y = *reinterpret_cast<const uint32_t*>(&o1);
            *(uint2*)(yp + l0) = ov;
        }
        dl4 = dl4n; uu = uun; B4 = B4n; C4 = C4n; zz = zzn;
    }
}

// ---------------- launch ----------------------------------------------------
extern "C" void kernel_launch(void* const* d_in, const int* in_sizes, int n_in,
                              void* d_out, int out_size) {
    (void)in_sizes; (void)n_in; (void)out_size;
    const float* hidden = (const float*)d_in[0];
    const float* Win = (const float*)d_in[1];
    const float* Wx = (const float*)d_in[2];
    const float* Wdt = (const float*)d_in[3];
    const float* dt_bias = (const float*)d_in[4];
    const float* Wout = (const float*)d_in[5];
    const float* dwk = (const float*)d_in[6];
    const float* dwb = (const float*)d_in[7];
    const float* A_log = (const float*)d_in[8];
    const float* Dskip = (const float*)d_in[9];
    float* out = (float*)d_out;

    float *xdblT, *deltaT, *part, *part4;
    cudaGetSymbolAddress((void**)&xdblT, g_xdblT);
    cudaGetSymbolAddress((void**)&deltaT, g_deltaT);
    cudaGetSymbolAddress((void**)&part, g_part);
    cudaGetSymbolAddress((void**)&part4, g_part4);

    __half *xz16, *WinT, *WxT, *WdtT, *WoutT, *h16, *xc16, *xcT, *zT, *dt16, *yT, *y16;
    cudaGetSymbolAddress((void**)&xz16, g_xz16);
    cudaGetSymbolAddress((void**)&WinT, g_WinT);
    cudaGetSymbolAddress((void**)&WxT, g_WxT);
    cudaGetSymbolAddress((void**)&WdtT, g_WdtT);
    cudaGetSymbolAddress((void**)&WoutT, g_WoutT);
    cudaGetSymbolAddress((void**)&h16, g_h);
    cudaGetSymbolAddress((void**)&xc16, g_xc);
    cudaGetSymbolAddress((void**)&xcT, g_xcT);
    cudaGetSymbolAddress((void**)&zT, g_zT);
    cudaGetSymbolAddress((void**)&dt16, g_dt);
    cudaGetSymbolAddress((void**)&yT, g_yT);
    cudaGetSymbolAddress((void**)&y16, g_y);

    cudaFuncSetAttribute(mma_gemm<0>, cudaFuncAttributeMaxDynamicSharedMemorySize, GSMEM);
    cudaFuncSetAttribute(mma_gemm<2>, cudaFuncAttributeMaxDynamicSharedMemorySize, GSMEM);
    cudaFuncSetAttribute(mma_gemm<3>, cudaFuncAttributeMaxDynamicSharedMemorySize, GSMEM);

    const dim3 tb(32, 8);

    // 0: all weight transposes (batched)
    convT_all<<<CONVT_ALL_BLOCKS, tb>>>(Win, WinT, Wx, WxT, Wdt, WdtT, Wout, WoutT);

    // 1: hidden -> fp16
    convA_kernel<<<(MROWS * DM / 4) / 256, 256>>>(hidden, h16, DM, DM);

    // 2: GEMM1: xz16 = hidden @ Win  (M=2048, N=4096, K=1024), fp16 out
    mma_gemm<3><<<dim3(4096 / 128, MROWS / 128, 1), 256, GSMEM>>>(
        h16, WinT, (float*)xz16, MROWS, 2 * DI, DM, DM / 32, nullptr);

    // 3: fused conv+silu -> xc16 [bl,d], xcT [d,bl], zT [d,bl]   [profiled]
    conv_fuse_kernel<<<dim3(DI / 32, MROWS / 32), tb>>>(
        xz16, dwk, dwb, xc16, xcT, zT);

    // 4: GEMM2T: (M=128, N=2048(bl), K=2048), split-K x8
    mma_gemm<0><<<dim3(MROWS / 128, 1, 8), 256, GSMEM>>>(
        WxT, xc16, part, 128, MROWS, DI, (DI / 32) / 8, nullptr);

    // 5: reduce + dt fp16 transpose
    reduce8T_kernel<<<(96 * (MROWS / 4) + 255) / 256, 256>>>(part, xdblT, dt16);

    // 6: GEMM3T: deltaT[d, bl] = softplus(Wdt^T @ dt^T + bias[d])  (K=64)
    mma_gemm<2><<<dim3(MROWS / 128, DI / 128, 1), 256, GSMEM>>>(
        WdtT, dt16, deltaT, DI, MROWS, DR, DR / 32, dt_bias);

    // 7: selective scan -> yT
    scanT_kernel<<<256, 256>>>(xcT, xdblT, deltaT, zT, A_log, Dskip, yT);

    // 8: yT -> y16 [bl, d]
    transpose_h2h<<<dim3(MROWS / 32, DI / 32), tb>>>(yT, y16, DI, MROWS);

    // 9,10: GEMM4: out = y @ Wout  (M=2048, N=1024, K=2048), split-K x2 + reduce
    mma_gemm<0><<<dim3(DM / 128, MROWS / 128, 2), 256, GSMEM>>>(
        y16, WoutT, part4, MROWS, DM, DI, (DI / 32) / 2, nullptr);
    reduce2_kernel<<<(MROWS * DM / 4) / 256, 256>>>(part4, out);
}